// round 1
// baseline (speedup 1.0000x reference)
#include <cuda_runtime.h>

#define B_  4
#define T_  2048
#define D_  1024
#define H_  16
#define DK_ 64
#define N3_ 3072
#define M_  (B_*T_)   // 8192

// Scratch (device globals; no allocations allowed)
__device__ float g_q[B_*H_*T_*DK_];   // (b,h,t,d) pre-scaled by 1/8
__device__ float g_k[B_*H_*T_*DK_];
__device__ float g_v[B_*H_*T_*DK_];
__device__ float g_ctx[M_*D_];        // (b,t,D)

// ---------------------------------------------------------------------------
// 128x128x8 register-blocked SGEMM, QKV epilogue (scatter into q/k/v heads)
// A: x (M_ x D_) row-major, Bm: w_qkv (D_ x N3_) row-major
// ---------------------------------------------------------------------------
__global__ __launch_bounds__(256) void sgemm_qkv(const float* __restrict__ A,
                                                 const float* __restrict__ Bm,
                                                 const float* __restrict__ bias) {
    __shared__ float As[8][128];
    __shared__ float Bs[8][128];
    const int K = D_, N = N3_;
    const int tid = threadIdx.x;
    const int bx = blockIdx.x, by = blockIdx.y;
    const int tx = tid & 15, ty = tid >> 4;

    float acc[8][8];
#pragma unroll
    for (int i = 0; i < 8; i++)
#pragma unroll
        for (int j = 0; j < 8; j++) acc[i][j] = 0.f;

    const int a_row = tid >> 1, a_col = (tid & 1) * 4;
    const int b_row = tid >> 5, b_col = (tid & 31) * 4;
    const float* Ap = A + (size_t)(by * 128 + a_row) * K + a_col;
    const float* Bp = Bm + (size_t)b_row * N + bx * 128 + b_col;

    for (int k0 = 0; k0 < K; k0 += 8) {
        float4 av = *(const float4*)Ap;
        float4 bv = *(const float4*)Bp;
        As[a_col + 0][a_row] = av.x;
        As[a_col + 1][a_row] = av.y;
        As[a_col + 2][a_row] = av.z;
        As[a_col + 3][a_row] = av.w;
        *(float4*)&Bs[b_row][b_col] = bv;
        __syncthreads();
#pragma unroll
        for (int k = 0; k < 8; k++) {
            float4 a0 = *(const float4*)&As[k][ty * 4];
            float4 a1 = *(const float4*)&As[k][64 + ty * 4];
            float4 b0 = *(const float4*)&Bs[k][tx * 4];
            float4 b1 = *(const float4*)&Bs[k][64 + tx * 4];
            float ar[8] = {a0.x, a0.y, a0.z, a0.w, a1.x, a1.y, a1.z, a1.w};
            float br[8] = {b0.x, b0.y, b0.z, b0.w, b1.x, b1.y, b1.z, b1.w};
#pragma unroll
            for (int i = 0; i < 8; i++)
#pragma unroll
                for (int j = 0; j < 8; j++) acc[i][j] += ar[i] * br[j];
        }
        __syncthreads();
        Ap += 8;
        Bp += (size_t)8 * N;
    }

#pragma unroll
    for (int i = 0; i < 8; i++) {
        int m = by * 128 + ((i < 4) ? ty * 4 + i : 64 + ty * 4 + (i - 4));
        int bidx = m >> 11;       // / T_
        int t = m & (T_ - 1);
#pragma unroll
        for (int j = 0; j < 8; j++) {
            int n = bx * 128 + ((j < 4) ? tx * 4 + j : 64 + tx * 4 + (j - 4));
            float val = acc[i][j] + bias[n];
            int part = n >> 10;           // 0=q,1=k,2=v
            int c = n & (D_ - 1);
            int h = c >> 6, d = c & 63;
            float* dst = (part == 0) ? g_q : (part == 1) ? g_k : g_v;
            if (part == 0) val *= 0.125f;  // fold 1/sqrt(d_k)
            dst[(((size_t)(bidx * H_ + h)) * T_ + t) * DK_ + d] = val;
        }
    }
}

// ---------------------------------------------------------------------------
// 128x128x8 SGEMM for output projection: C = g_ctx @ w_out + b_out
// ---------------------------------------------------------------------------
__global__ __launch_bounds__(256) void sgemm_out(const float* __restrict__ Bm,
                                                 const float* __restrict__ bias,
                                                 float* __restrict__ C) {
    __shared__ float As[8][128];
    __shared__ float Bs[8][128];
    const int K = D_, N = D_;
    const int tid = threadIdx.x;
    const int bx = blockIdx.x, by = blockIdx.y;
    const int tx = tid & 15, ty = tid >> 4;

    float acc[8][8];
#pragma unroll
    for (int i = 0; i < 8; i++)
#pragma unroll
        for (int j = 0; j < 8; j++) acc[i][j] = 0.f;

    const int a_row = tid >> 1, a_col = (tid & 1) * 4;
    const int b_row = tid >> 5, b_col = (tid & 31) * 4;
    const float* Ap = g_ctx + (size_t)(by * 128 + a_row) * K + a_col;
    const float* Bp = Bm + (size_t)b_row * N + bx * 128 + b_col;

    for (int k0 = 0; k0 < K; k0 += 8) {
        float4 av = *(const float4*)Ap;
        float4 bv = *(const float4*)Bp;
        As[a_col + 0][a_row] = av.x;
        As[a_col + 1][a_row] = av.y;
        As[a_col + 2][a_row] = av.z;
        As[a_col + 3][a_row] = av.w;
        *(float4*)&Bs[b_row][b_col] = bv;
        __syncthreads();
#pragma unroll
        for (int k = 0; k < 8; k++) {
            float4 a0 = *(const float4*)&As[k][ty * 4];
            float4 a1 = *(const float4*)&As[k][64 + ty * 4];
            float4 b0 = *(const float4*)&Bs[k][tx * 4];
            float4 b1 = *(const float4*)&Bs[k][64 + tx * 4];
            float ar[8] = {a0.x, a0.y, a0.z, a0.w, a1.x, a1.y, a1.z, a1.w};
            float br[8] = {b0.x, b0.y, b0.z, b0.w, b1.x, b1.y, b1.z, b1.w};
#pragma unroll
            for (int i = 0; i < 8; i++)
#pragma unroll
                for (int j = 0; j < 8; j++) acc[i][j] += ar[i] * br[j];
        }
        __syncthreads();
        Ap += 8;
        Bp += (size_t)8 * N;
    }

#pragma unroll
    for (int i = 0; i < 8; i++) {
        int m = by * 128 + ((i < 4) ? ty * 4 + i : 64 + ty * 4 + (i - 4));
#pragma unroll
        for (int jf = 0; jf < 2; jf++) {
            int n = bx * 128 + jf * 64 + tx * 4;
            float4 ov;
            ov.x = acc[i][jf * 4 + 0] + bias[n + 0];
            ov.y = acc[i][jf * 4 + 1] + bias[n + 1];
            ov.z = acc[i][jf * 4 + 2] + bias[n + 2];
            ov.w = acc[i][jf * 4 + 3] + bias[n + 3];
            *(float4*)&C[(size_t)m * N + n] = ov;
        }
    }
}

// ---------------------------------------------------------------------------
// Flash attention, fp32. One CTA = 64 q-rows of one (b,h). KV tiles of 64.
// Dynamic smem 64KB: Qs[d][r], Ks[d][c], Vs[kv][d], Ps[r][kv], each 64x64.
// ---------------------------------------------------------------------------
__global__ __launch_bounds__(256) void attn_kernel() {
    extern __shared__ float sm[];
    float* Qs = sm;            // transposed: Qs[d*64 + r]
    float* Ks = sm + 4096;     // transposed: Ks[d*64 + c]
    float* Vs = sm + 8192;     // Vs[kv*64 + d]
    float* Ps = sm + 12288;    // Ps[r*64 + kv]

    const int tid = threadIdx.x;
    const int tx = tid & 15, ty = tid >> 4;
    const int bh = blockIdx.y;
    const int t0 = blockIdx.x * 64;
    const float* qb = g_q + (size_t)bh * T_ * DK_;
    const float* kb = g_k + (size_t)bh * T_ * DK_;
    const float* vb = g_v + (size_t)bh * T_ * DK_;

    // Load Q tile transposed (scale already folded in at QKV epilogue)
#pragma unroll
    for (int it = 0; it < 4; it++) {
        int idx = it * 256 + tid;
        int r = idx >> 4, dg = (idx & 15) * 4;
        float4 qv = *(const float4*)&qb[(size_t)(t0 + r) * DK_ + dg];
        Qs[(dg + 0) * 64 + r] = qv.x;
        Qs[(dg + 1) * 64 + r] = qv.y;
        Qs[(dg + 2) * 64 + r] = qv.z;
        Qs[(dg + 3) * 64 + r] = qv.w;
    }

    float m_i[4], l_i[4], o[4][4];
#pragma unroll
    for (int i = 0; i < 4; i++) {
        m_i[i] = -1e30f;
        l_i[i] = 0.f;
#pragma unroll
        for (int j = 0; j < 4; j++) o[i][j] = 0.f;
    }

    for (int jt = 0; jt < T_ / 64; jt++) {
        __syncthreads();  // previous PV reads done; Qs writes ordered by next sync
#pragma unroll
        for (int it = 0; it < 4; it++) {
            int idx = it * 256 + tid;
            int r = idx >> 4, dg = (idx & 15) * 4;
            float4 kv4 = *(const float4*)&kb[(size_t)(jt * 64 + r) * DK_ + dg];
            Ks[(dg + 0) * 64 + r] = kv4.x;
            Ks[(dg + 1) * 64 + r] = kv4.y;
            Ks[(dg + 2) * 64 + r] = kv4.z;
            Ks[(dg + 3) * 64 + r] = kv4.w;
            float4 vv4 = *(const float4*)&vb[(size_t)(jt * 64 + r) * DK_ + dg];
            *(float4*)&Vs[r * 64 + dg] = vv4;
        }
        __syncthreads();

        // S = Q K^T (64x64), thread owns rows ty*4.., cols tx*4..
        float s[4][4];
#pragma unroll
        for (int i = 0; i < 4; i++)
#pragma unroll
            for (int j = 0; j < 4; j++) s[i][j] = 0.f;
#pragma unroll
        for (int d = 0; d < 64; d++) {
            float4 qa = *(const float4*)&Qs[d * 64 + ty * 4];
            float4 ka = *(const float4*)&Ks[d * 64 + tx * 4];
            float aq[4] = {qa.x, qa.y, qa.z, qa.w};
            float ak[4] = {ka.x, ka.y, ka.z, ka.w};
#pragma unroll
            for (int i = 0; i < 4; i++)
#pragma unroll
                for (int j = 0; j < 4; j++) s[i][j] += aq[i] * ak[j];
        }

        // online softmax; row groups share ty -> reduce across 16 tx lanes
#pragma unroll
        for (int i = 0; i < 4; i++) {
            float mt = fmaxf(fmaxf(s[i][0], s[i][1]), fmaxf(s[i][2], s[i][3]));
#pragma unroll
            for (int off = 8; off > 0; off >>= 1)
                mt = fmaxf(mt, __shfl_xor_sync(0xffffffffu, mt, off));
            float mn = fmaxf(m_i[i], mt);
            float corr = __expf(m_i[i] - mn);
            m_i[i] = mn;
            float ls = 0.f;
#pragma unroll
            for (int j = 0; j < 4; j++) {
                s[i][j] = __expf(s[i][j] - mn);
                ls += s[i][j];
            }
#pragma unroll
            for (int off = 8; off > 0; off >>= 1)
                ls += __shfl_xor_sync(0xffffffffu, ls, off);
            l_i[i] = l_i[i] * corr + ls;
#pragma unroll
            for (int j = 0; j < 4; j++) o[i][j] *= corr;
            *(float4*)&Ps[(ty * 4 + i) * 64 + tx * 4] =
                make_float4(s[i][0], s[i][1], s[i][2], s[i][3]);
        }
        __syncthreads();

        // O += P @ V ; thread owns O rows ty*4.., cols tx*4..
#pragma unroll 8
        for (int kv = 0; kv < 64; kv++) {
            float4 vv = *(const float4*)&Vs[kv * 64 + tx * 4];
#pragma unroll
            for (int i = 0; i < 4; i++) {
                float p = Ps[(ty * 4 + i) * 64 + kv];
                o[i][0] += p * vv.x;
                o[i][1] += p * vv.y;
                o[i][2] += p * vv.z;
                o[i][3] += p * vv.w;
            }
        }
    }

    // write ctx (B,T,D) with head interleave
    const int b = bh >> 4, h = bh & 15;
#pragma unroll
    for (int i = 0; i < 4; i++) {
        float inv = 1.0f / l_i[i];
        int t = t0 + ty * 4 + i;
        float4 ov = make_float4(o[i][0] * inv, o[i][1] * inv, o[i][2] * inv,
                                o[i][3] * inv);
        *(float4*)&g_ctx[((size_t)(b * T_ + t)) * D_ + h * 64 + tx * 4] = ov;
    }
}

// ---------------------------------------------------------------------------
extern "C" void kernel_launch(void* const* d_in, const int* in_sizes, int n_in,
                              void* d_out, int out_size) {
    const float *x = nullptr, *w_qkv = nullptr, *b_qkv = nullptr,
                *w_out = nullptr, *b_out = nullptr;
    for (int i = 0; i < n_in; i++) {
        switch (in_sizes[i]) {
            case M_ * D_:   x = (const float*)d_in[i]; break;       // 8388608
            case D_ * N3_:  w_qkv = (const float*)d_in[i]; break;   // 3145728
            case N3_:       b_qkv = (const float*)d_in[i]; break;
            case D_ * D_:   w_out = (const float*)d_in[i]; break;   // 1048576
            case D_:        b_out = (const float*)d_in[i]; break;
        }
    }

    cudaFuncSetAttribute(attn_kernel,
                         cudaFuncAttributeMaxDynamicSharedMemorySize, 65536);

    sgemm_qkv<<<dim3(N3_ / 128, M_ / 128), 256>>>(x, w_qkv, b_qkv);
    attn_kernel<<<dim3(T_ / 64, B_ * H_), 256, 65536>>>();
    sgemm_out<<<dim3(D_ / 128, M_ / 128), 256>>>(w_out, b_out, (float*)d_out);
}

// round 4
// speedup vs baseline: 1.5450x; 1.5450x over previous
#include <cuda_runtime.h>
#include <stdint.h>

#define B_  4
#define T_  2048
#define D_  1024
#define H_  16
#define DK_ 64
#define N3_ 3072
#define M_  (B_*T_)   // 8192

// Scratch (device globals; no allocations allowed)
__device__ float g_q[B_*H_*T_*DK_];   // (b,h,t,d) pre-scaled by 1/8
__device__ float g_k[B_*H_*T_*DK_];
__device__ float g_v[B_*H_*T_*DK_];
__device__ float g_ctx[M_*D_];        // (b,t,D)

// ===========================================================================
// Helpers
// ===========================================================================
__device__ __forceinline__ void mma_tf32(float* c, const uint32_t* a,
                                         const uint32_t* b) {
    asm volatile(
        "mma.sync.aligned.m16n8k8.row.col.f32.tf32.tf32.f32 "
        "{%0,%1,%2,%3}, {%4,%5,%6,%7}, {%8,%9}, {%0,%1,%2,%3};\n"
        : "+f"(c[0]), "+f"(c[1]), "+f"(c[2]), "+f"(c[3])
        : "r"(a[0]), "r"(a[1]), "r"(a[2]), "r"(a[3]), "r"(b[0]), "r"(b[1]));
}

// hi = rna_tf32(x); lo = rna_tf32(x - hi). hi+lo carries ~22 significand bits.
__device__ __forceinline__ void split_tf32(float x, uint32_t& hi, uint32_t& lo) {
    uint32_t h;
    asm("cvt.rna.tf32.f32 %0, %1;" : "=r"(h) : "f"(x));
    float r = x - __uint_as_float(h);
    uint32_t l;
    asm("cvt.rna.tf32.f32 %0, %1;" : "=r"(l) : "f"(r));
    hi = h; lo = l;
}

__device__ __forceinline__ void split4(float4 v, float4& h4, float4& l4) {
    uint32_t h, l;
    split_tf32(v.x, h, l); h4.x = __uint_as_float(h); l4.x = __uint_as_float(l);
    split_tf32(v.y, h, l); h4.y = __uint_as_float(h); l4.y = __uint_as_float(l);
    split_tf32(v.z, h, l); h4.z = __uint_as_float(h); l4.z = __uint_as_float(l);
    split_tf32(v.w, h, l); h4.w = __uint_as_float(h); l4.w = __uint_as_float(l);
}

// ===========================================================================
// 3xTF32 GEMM: C[M,N] = A[M,1024] @ B[1024,N] + bias   (full fp32 accuracy)
// CTA tile 128x128, BK=16, register-prefetch pipeline with hi/lo smem tiles.
// EPI 0: scatter into g_q/g_k/g_v (q scaled by 1/8); EPI 1: plain store.
// ===========================================================================
#define BK  16
#define ALD 20     // conflict-free for A frag pattern (gid*20+tig distinct mod 32)
#define BLD 136    // conflict-free for B frag pattern

template<int N, int EPI>
__global__ __launch_bounds__(256) void gemm_tc(const float* __restrict__ A_in,
                                               const float* __restrict__ Bg,
                                               const float* __restrict__ bias,
                                               float* __restrict__ C) {
    __shared__ float Ah[128 * ALD], Al[128 * ALD];
    __shared__ float Bh[BK * BLD],  Bl[BK * BLD];

    const int tid = threadIdx.x;
    const int wid = tid >> 5, lane = tid & 31;
    const int gid = lane >> 2, tig = lane & 3;
    const int wm = wid & 1, wn = wid >> 1;      // 2 x 4 warp grid
    const int bx = blockIdx.x, by = blockIdx.y;

    const float* A = (EPI == 1) ? (const float*)g_ctx : A_in;
    const float* Abase = A + (size_t)(by * 128) * D_;
    const float* Bbase = Bg + bx * 128;

    // staging coordinates (512 float4 slots per operand, 2 per thread)
    const int rowA = tid >> 2, kA = (tid & 3) * 4;            // rows rowA, rowA+64
    const int krB = tid >> 5, cB = (tid & 31) * 4;            // k-rows krB, krB+8

    float c[4][4][4];
#pragma unroll
    for (int mt = 0; mt < 4; mt++)
#pragma unroll
        for (int nt = 0; nt < 4; nt++)
#pragma unroll
            for (int i = 0; i < 4; i++) c[mt][nt][i] = 0.f;

    float4 pa0, pa1, pb0, pb1;
    auto ldg_stage = [&](int k0) {
        pa0 = *(const float4*)(Abase + (size_t)rowA * D_ + k0 + kA);
        pa1 = *(const float4*)(Abase + (size_t)(rowA + 64) * D_ + k0 + kA);
        pb0 = *(const float4*)(Bbase + (size_t)(k0 + krB) * N + cB);
        pb1 = *(const float4*)(Bbase + (size_t)(k0 + krB + 8) * N + cB);
    };
    auto sts_stage = [&]() {
        float4 h4, l4;
        split4(pa0, h4, l4);
        *(float4*)&Ah[rowA * ALD + kA] = h4;
        *(float4*)&Al[rowA * ALD + kA] = l4;
        split4(pa1, h4, l4);
        *(float4*)&Ah[(rowA + 64) * ALD + kA] = h4;
        *(float4*)&Al[(rowA + 64) * ALD + kA] = l4;
        split4(pb0, h4, l4);
        *(float4*)&Bh[krB * BLD + cB] = h4;
        *(float4*)&Bl[krB * BLD + cB] = l4;
        split4(pb1, h4, l4);
        *(float4*)&Bh[(krB + 8) * BLD + cB] = h4;
        *(float4*)&Bl[(krB + 8) * BLD + cB] = l4;
    };

    const int NK = D_ / BK;      // 64
    ldg_stage(0);
    sts_stage();
    __syncthreads();

    for (int it = 0; it < NK; it++) {
        if (it + 1 < NK) ldg_stage((it + 1) * BK);

#pragma unroll
        for (int kk = 0; kk < 2; kk++) {
            uint32_t ah[4][4], al[4][4], bh[4][2], bl[4][2];
#pragma unroll
            for (int mt = 0; mt < 4; mt++) {
                int r0 = wm * 64 + mt * 16 + gid;
                int k = kk * 8 + tig;
                ah[mt][0] = __float_as_uint(Ah[r0 * ALD + k]);
                ah[mt][1] = __float_as_uint(Ah[(r0 + 8) * ALD + k]);
                ah[mt][2] = __float_as_uint(Ah[r0 * ALD + k + 4]);
                ah[mt][3] = __float_as_uint(Ah[(r0 + 8) * ALD + k + 4]);
                al[mt][0] = __float_as_uint(Al[r0 * ALD + k]);
                al[mt][1] = __float_as_uint(Al[(r0 + 8) * ALD + k]);
                al[mt][2] = __float_as_uint(Al[r0 * ALD + k + 4]);
                al[mt][3] = __float_as_uint(Al[(r0 + 8) * ALD + k + 4]);
            }
#pragma unroll
            for (int nt = 0; nt < 4; nt++) {
                int col = wn * 32 + nt * 8 + gid;
                int k = kk * 8 + tig;
                bh[nt][0] = __float_as_uint(Bh[k * BLD + col]);
                bh[nt][1] = __float_as_uint(Bh[(k + 4) * BLD + col]);
                bl[nt][0] = __float_as_uint(Bl[k * BLD + col]);
                bl[nt][1] = __float_as_uint(Bl[(k + 4) * BLD + col]);
            }
#pragma unroll
            for (int mt = 0; mt < 4; mt++)
#pragma unroll
                for (int nt = 0; nt < 4; nt++) {
                    mma_tf32(c[mt][nt], ah[mt], bh[nt]);
                    mma_tf32(c[mt][nt], ah[mt], bl[nt]);
                    mma_tf32(c[mt][nt], al[mt], bh[nt]);
                }
        }
        __syncthreads();
        if (it + 1 < NK) {
            sts_stage();
            __syncthreads();
        }
    }

    // Epilogue: direct float2 stores from C fragments
#pragma unroll
    for (int mt = 0; mt < 4; mt++) {
#pragma unroll
        for (int nt = 0; nt < 4; nt++) {
            int col = bx * 128 + wn * 32 + nt * 8 + 2 * tig;
            float bv0 = bias[col], bv1 = bias[col + 1];
#pragma unroll
            for (int half = 0; half < 2; half++) {
                int m = by * 128 + wm * 64 + mt * 16 + gid + half * 8;
                float v0 = c[mt][nt][half * 2 + 0] + bv0;
                float v1 = c[mt][nt][half * 2 + 1] + bv1;
                if (EPI == 0) {
                    int part = col >> 10;
                    int hh = (col >> 6) & 15;
                    int d = col & 63;
                    int b = m >> 11, t = m & (T_ - 1);
                    float* dst = (part == 0) ? g_q : (part == 1) ? g_k : g_v;
                    if (part == 0) { v0 *= 0.125f; v1 *= 0.125f; }
                    *(float2*)&dst[(((size_t)(b * H_ + hh)) * T_ + t) * DK_ + d] =
                        make_float2(v0, v1);
                } else {
                    *(float2*)&C[(size_t)m * N + col] = make_float2(v0, v1);
                }
            }
        }
    }
}

// ===========================================================================
// Flash attention on 3xTF32 mma.sync.
// CTA: 128 q rows of one (b,h); 8 warps, warp = 16 rows x full 64-col KV tile.
// K/V split hi/lo ONCE at staging (8-warp reuse); Q split once to registers.
// Q smem region reused as fp32 P staging (warp-private strips).
// ===========================================================================
#define QLD 68    // conflict-free: (gid*68+tig) mod 32 = gid*4+tig, distinct
#define KLDK 68   // K frags: (gid*68+tig) -> distinct banks
#define KLDV 72   // V frags: (tig*72+gid) -> tig*8+gid, distinct banks
#define ATT_SMEM ((128*QLD + 2*64*KLDK + 2*64*KLDV) * 4)   // 106496 B

__global__ __launch_bounds__(256) void attn_kernel() {
    extern __shared__ float sm[];
    float* QPs = sm;                        // 128 x QLD : Q, later P (fp32)
    float* Kh  = sm + 128 * QLD;            // 64 x KLDK
    float* Kl  = Kh + 64 * KLDK;
    float* Vh  = Kl + 64 * KLDK;            // 64 x KLDV
    float* Vl  = Vh + 64 * KLDV;

    const int tid = threadIdx.x;
    const int wid = tid >> 5, lane = tid & 31;
    const int gid = lane >> 2, tig = lane & 3;
    const int bh = blockIdx.y;
    const int t0 = blockIdx.x * 128;
    const float* qb = g_q + (size_t)bh * T_ * DK_;
    const float* kb = g_k + (size_t)bh * T_ * DK_;
    const float* vb = g_v + (size_t)bh * T_ * DK_;

    // ---- load Q tile (fp32) to smem, prefetch + split this warp's A-frags
#pragma unroll
    for (int i = 0; i < 8; i++) {
        int idx = i * 256 + tid;
        int row = idx >> 4, dg = (idx & 15) * 4;
        *(float4*)&QPs[row * QLD + dg] =
            *(const float4*)&qb[(size_t)(t0 + row) * DK_ + dg];
    }
    __syncthreads();

    uint32_t qh[8][4], ql[8][4];
    {
        const int r0 = wid * 16 + gid;
#pragma unroll
        for (int kk = 0; kk < 8; kk++) {
            split_tf32(QPs[r0 * QLD + kk * 8 + tig],        qh[kk][0], ql[kk][0]);
            split_tf32(QPs[(r0 + 8) * QLD + kk * 8 + tig],  qh[kk][1], ql[kk][1]);
            split_tf32(QPs[r0 * QLD + kk * 8 + tig + 4],    qh[kk][2], ql[kk][2]);
            split_tf32(QPs[(r0 + 8) * QLD + kk * 8 + tig + 4], qh[kk][3], ql[kk][3]);
        }
    }

    float m_i[2] = {-1e30f, -1e30f};
    float l_i[2] = {0.f, 0.f};
    float oc[8][4];
#pragma unroll
    for (int j = 0; j < 8; j++)
#pragma unroll
        for (int i = 0; i < 4; i++) oc[j][i] = 0.f;

    for (int kt = 0; kt < T_ / 64; kt++) {
        __syncthreads();   // prior tile's K/V reads done by all warps
        // ---- stage K,V: LDG fp32 -> split hi/lo -> STS (once per CTA)
#pragma unroll
        for (int i = 0; i < 4; i++) {
            int idx = i * 256 + tid;
            int row = idx >> 4, dg = (idx & 15) * 4;
            float4 h4, l4;
            float4 kv4 = *(const float4*)&kb[(size_t)(kt * 64 + row) * DK_ + dg];
            split4(kv4, h4, l4);
            *(float4*)&Kh[row * KLDK + dg] = h4;
            *(float4*)&Kl[row * KLDK + dg] = l4;
            float4 vv4 = *(const float4*)&vb[(size_t)(kt * 64 + row) * DK_ + dg];
            split4(vv4, h4, l4);
            *(float4*)&Vh[row * KLDV + dg] = h4;
            *(float4*)&Vl[row * KLDV + dg] = l4;
        }
        __syncthreads();

        // ---- S = Q @ K^T  (warp: 16 rows x 64 cols), 3 passes
        float sc[8][4];
#pragma unroll
        for (int j = 0; j < 8; j++)
#pragma unroll
            for (int i = 0; i < 4; i++) sc[j][i] = 0.f;
#pragma unroll
        for (int kk = 0; kk < 8; kk++) {
            uint32_t bhf[8][2], blf[8][2];
#pragma unroll
            for (int j = 0; j < 8; j++) {
                int r = j * 8 + gid, k = kk * 8 + tig;
                bhf[j][0] = __float_as_uint(Kh[r * KLDK + k]);
                bhf[j][1] = __float_as_uint(Kh[r * KLDK + k + 4]);
                blf[j][0] = __float_as_uint(Kl[r * KLDK + k]);
                blf[j][1] = __float_as_uint(Kl[r * KLDK + k + 4]);
            }
#pragma unroll
            for (int j = 0; j < 8; j++) {
                mma_tf32(sc[j], qh[kk], bhf[j]);
                mma_tf32(sc[j], qh[kk], blf[j]);
                mma_tf32(sc[j], ql[kk], bhf[j]);
            }
        }

        // ---- online softmax (rows gid and gid+8 of this warp's strip)
#pragma unroll
        for (int h2 = 0; h2 < 2; h2++) {
            float tmax = -1e30f;
#pragma unroll
            for (int j = 0; j < 8; j++)
                tmax = fmaxf(tmax, fmaxf(sc[j][2 * h2], sc[j][2 * h2 + 1]));
            tmax = fmaxf(tmax, __shfl_xor_sync(0xffffffffu, tmax, 1));
            tmax = fmaxf(tmax, __shfl_xor_sync(0xffffffffu, tmax, 2));
            float mn = fmaxf(m_i[h2], tmax);
            float corr = __expf(m_i[h2] - mn);
            m_i[h2] = mn;
            float ls = 0.f;
#pragma unroll
            for (int j = 0; j < 8; j++) {
                float e0 = __expf(sc[j][2 * h2] - mn);
                float e1 = __expf(sc[j][2 * h2 + 1] - mn);
                sc[j][2 * h2] = e0;
                sc[j][2 * h2 + 1] = e1;
                ls += e0 + e1;
            }
            ls += __shfl_xor_sync(0xffffffffu, ls, 1);
            ls += __shfl_xor_sync(0xffffffffu, ls, 2);
            l_i[h2] = l_i[h2] * corr + ls;
#pragma unroll
            for (int j = 0; j < 8; j++) {
                oc[j][2 * h2] *= corr;
                oc[j][2 * h2 + 1] *= corr;
            }
            int row = wid * 16 + gid + h2 * 8;
#pragma unroll
            for (int j = 0; j < 8; j++)
                *(float2*)&QPs[row * QLD + j * 8 + 2 * tig] =
                    make_float2(sc[j][2 * h2], sc[j][2 * h2 + 1]);
        }
        __syncwarp();

        // ---- O += P @ V, 3 passes
#pragma unroll
        for (int kk = 0; kk < 8; kk++) {
            uint32_t ph[4], pl[4];
            const int r0 = wid * 16 + gid;
            split_tf32(QPs[r0 * QLD + kk * 8 + tig],           ph[0], pl[0]);
            split_tf32(QPs[(r0 + 8) * QLD + kk * 8 + tig],     ph[1], pl[1]);
            split_tf32(QPs[r0 * QLD + kk * 8 + tig + 4],       ph[2], pl[2]);
            split_tf32(QPs[(r0 + 8) * QLD + kk * 8 + tig + 4], ph[3], pl[3]);
            uint32_t bhf[8][2], blf[8][2];
#pragma unroll
            for (int j = 0; j < 8; j++) {
                int k = kk * 8 + tig, n = j * 8 + gid;
                bhf[j][0] = __float_as_uint(Vh[k * KLDV + n]);
                bhf[j][1] = __float_as_uint(Vh[(k + 4) * KLDV + n]);
                blf[j][0] = __float_as_uint(Vl[k * KLDV + n]);
                blf[j][1] = __float_as_uint(Vl[(k + 4) * KLDV + n]);
            }
#pragma unroll
            for (int j = 0; j < 8; j++) {
                mma_tf32(oc[j], ph, bhf[j]);
                mma_tf32(oc[j], ph, blf[j]);
                mma_tf32(oc[j], pl, bhf[j]);
            }
        }
        __syncwarp();   // P reads done before next tile overwrites (warp-local)
    }

    // ---- finalize and write ctx (B,T,D) with head interleave
    const int b = bh >> 4, h = bh & 15;
    float inv0 = 1.0f / l_i[0], inv1 = 1.0f / l_i[1];
#pragma unroll
    for (int half = 0; half < 2; half++) {
        int t = t0 + wid * 16 + gid + half * 8;
        float inv = half ? inv1 : inv0;
        float* dst = &g_ctx[((size_t)(b * T_ + t)) * D_ + h * 64];
#pragma unroll
        for (int j = 0; j < 8; j++)
            *(float2*)&dst[j * 8 + 2 * tig] =
                make_float2(oc[j][half * 2] * inv, oc[j][half * 2 + 1] * inv);
    }
}

// ---------------------------------------------------------------------------
extern "C" void kernel_launch(void* const* d_in, const int* in_sizes, int n_in,
                              void* d_out, int out_size) {
    const float *x = nullptr, *w_qkv = nullptr, *b_qkv = nullptr,
                *w_out = nullptr, *b_out = nullptr;
    for (int i = 0; i < n_in; i++) {
        switch (in_sizes[i]) {
            case M_ * D_:   x = (const float*)d_in[i]; break;
            case D_ * N3_:  w_qkv = (const float*)d_in[i]; break;
            case N3_:       b_qkv = (const float*)d_in[i]; break;
            case D_ * D_:   w_out = (const float*)d_in[i]; break;
            case D_:        b_out = (const float*)d_in[i]; break;
        }
    }

    cudaFuncSetAttribute(attn_kernel,
                         cudaFuncAttributeMaxDynamicSharedMemorySize, ATT_SMEM);

    gemm_tc<N3_, 0><<<dim3(N3_ / 128, M_ / 128), 256>>>(x, w_qkv, b_qkv, nullptr);
    attn_kernel<<<dim3(T_ / 128, B_ * H_), 256, ATT_SMEM>>>();
    gemm_tc<D_, 1><<<dim3(D_ / 128, M_ / 128), 256>>>(nullptr, w_out, b_out,
                                                      (float*)d_out);
}

// round 5
// speedup vs baseline: 2.1910x; 1.4181x over previous
#include <cuda_runtime.h>
#include <stdint.h>

#define B_  4
#define T_  2048
#define D_  1024
#define H_  16
#define DK_ 64
#define N3_ 3072
#define M_  (B_*T_)   // 8192

// Scratch (device globals; no allocations allowed)
__device__ float g_q[B_*H_*T_*DK_];   // (b,h,t,d) pre-scaled by 1/8
__device__ float g_k[B_*H_*T_*DK_];
__device__ float g_v[B_*H_*T_*DK_];
__device__ float g_ctx[M_*D_];        // (b,t,D)

// ===========================================================================
// Helpers
// ===========================================================================
__device__ __forceinline__ void mma_tf32(float* c, const uint32_t* a,
                                         const uint32_t* b) {
    asm volatile(
        "mma.sync.aligned.m16n8k8.row.col.f32.tf32.tf32.f32 "
        "{%0,%1,%2,%3}, {%4,%5,%6,%7}, {%8,%9}, {%0,%1,%2,%3};\n"
        : "+f"(c[0]), "+f"(c[1]), "+f"(c[2]), "+f"(c[3])
        : "r"(a[0]), "r"(a[1]), "r"(a[2]), "r"(a[3]), "r"(b[0]), "r"(b[1]));
}

__device__ __forceinline__ uint32_t rna(float x) {
    uint32_t r;
    asm("cvt.rna.tf32.f32 %0, %1;" : "=r"(r) : "f"(x));
    return r;
}

// hi = rna_tf32(x); lo = rna_tf32(x - hi). hi+lo carries ~22 significand bits.
__device__ __forceinline__ void split_tf32(float x, uint32_t& hi, uint32_t& lo) {
    uint32_t h = rna(x);
    float r = x - __uint_as_float(h);
    hi = h; lo = rna(r);
}

__device__ __forceinline__ void split4(float4 v, float4& h4, float4& l4) {
    uint32_t h, l;
    split_tf32(v.x, h, l); h4.x = __uint_as_float(h); l4.x = __uint_as_float(l);
    split_tf32(v.y, h, l); h4.y = __uint_as_float(h); l4.y = __uint_as_float(l);
    split_tf32(v.z, h, l); h4.z = __uint_as_float(h); l4.z = __uint_as_float(l);
    split_tf32(v.w, h, l); h4.w = __uint_as_float(h); l4.w = __uint_as_float(l);
}

// ===========================================================================
// 3xTF32 GEMM: C[M,N] = A[M,1024] @ B[1024,N] + bias   (full fp32 accuracy)
// CTA tile 128x128, BK=16, DOUBLE-BUFFERED hi/lo smem, 2 CTAs/SM, 1 sync/iter.
// EPI 0: scatter into g_q/g_k/g_v (q scaled by 1/8); EPI 1: plain store.
// ===========================================================================
#define BK  16
#define ALD 20
#define BLD 136
#define ASZ (128 * ALD)       // 2560 floats per buffer
#define BSZ (BK * BLD)        // 2176 floats per buffer
#define GEMM_SMEM ((4 * ASZ + 4 * BSZ) * 4)    // 75776 bytes

template<int N, int EPI>
__global__ __launch_bounds__(256, 2) void gemm_tc(const float* __restrict__ A_in,
                                                  const float* __restrict__ Bg,
                                                  const float* __restrict__ bias,
                                                  float* __restrict__ C) {
    extern __shared__ float smf[];
    float* Ah0 = smf;                 // [2][ASZ]
    float* Al0 = smf + 2 * ASZ;       // [2][ASZ]
    float* Bh0 = smf + 4 * ASZ;       // [2][BSZ]
    float* Bl0 = smf + 4 * ASZ + 2 * BSZ;

    const int tid = threadIdx.x;
    const int wid = tid >> 5, lane = tid & 31;
    const int gid = lane >> 2, tig = lane & 3;
    const int wm = wid & 1, wn = wid >> 1;      // 2 x 4 warp grid
    const int bx = blockIdx.x, by = blockIdx.y;

    const float* A = (EPI == 1) ? (const float*)g_ctx : A_in;
    const float* Abase = A + (size_t)(by * 128) * D_;
    const float* Bbase = Bg + bx * 128;

    const int rowA = tid >> 2, kA = (tid & 3) * 4;   // rows rowA, rowA+64
    const int krB = tid >> 5, cB = (tid & 31) * 4;   // k-rows krB, krB+8

    float c[4][4][4];
#pragma unroll
    for (int mt = 0; mt < 4; mt++)
#pragma unroll
        for (int nt = 0; nt < 4; nt++)
#pragma unroll
            for (int i = 0; i < 4; i++) c[mt][nt][i] = 0.f;

    float4 pa0, pa1, pb0, pb1;
    auto ldg_stage = [&](int k0) {
        pa0 = *(const float4*)(Abase + (size_t)rowA * D_ + k0 + kA);
        pa1 = *(const float4*)(Abase + (size_t)(rowA + 64) * D_ + k0 + kA);
        pb0 = *(const float4*)(Bbase + (size_t)(k0 + krB) * N + cB);
        pb1 = *(const float4*)(Bbase + (size_t)(k0 + krB + 8) * N + cB);
    };
    auto sts_stage = [&](int buf) {
        float* Ah = Ah0 + buf * ASZ;
        float* Al = Al0 + buf * ASZ;
        float* Bh = Bh0 + buf * BSZ;
        float* Bl = Bl0 + buf * BSZ;
        float4 h4, l4;
        split4(pa0, h4, l4);
        *(float4*)&Ah[rowA * ALD + kA] = h4;
        *(float4*)&Al[rowA * ALD + kA] = l4;
        split4(pa1, h4, l4);
        *(float4*)&Ah[(rowA + 64) * ALD + kA] = h4;
        *(float4*)&Al[(rowA + 64) * ALD + kA] = l4;
        split4(pb0, h4, l4);
        *(float4*)&Bh[krB * BLD + cB] = h4;
        *(float4*)&Bl[krB * BLD + cB] = l4;
        split4(pb1, h4, l4);
        *(float4*)&Bh[(krB + 8) * BLD + cB] = h4;
        *(float4*)&Bl[(krB + 8) * BLD + cB] = l4;
    };

    const int NK = D_ / BK;      // 64
    ldg_stage(0);
    sts_stage(0);
    __syncthreads();

    for (int it = 0; it < NK; it++) {
        const int buf = it & 1;
        if (it + 1 < NK) ldg_stage((it + 1) * BK);

        const float* Ah = Ah0 + buf * ASZ;
        const float* Al = Al0 + buf * ASZ;
        const float* Bh = Bh0 + buf * BSZ;
        const float* Bl = Bl0 + buf * BSZ;
#pragma unroll
        for (int kk = 0; kk < 2; kk++) {
            const int k = kk * 8 + tig;
            uint32_t bh[4][2], bl[4][2];
#pragma unroll
            for (int nt = 0; nt < 4; nt++) {
                int col = wn * 32 + nt * 8 + gid;
                bh[nt][0] = __float_as_uint(Bh[k * BLD + col]);
                bh[nt][1] = __float_as_uint(Bh[(k + 4) * BLD + col]);
                bl[nt][0] = __float_as_uint(Bl[k * BLD + col]);
                bl[nt][1] = __float_as_uint(Bl[(k + 4) * BLD + col]);
            }
#pragma unroll
            for (int mt = 0; mt < 4; mt++) {
                int r0 = wm * 64 + mt * 16 + gid;
                uint32_t ah[4], al[4];
                ah[0] = __float_as_uint(Ah[r0 * ALD + k]);
                ah[1] = __float_as_uint(Ah[(r0 + 8) * ALD + k]);
                ah[2] = __float_as_uint(Ah[r0 * ALD + k + 4]);
                ah[3] = __float_as_uint(Ah[(r0 + 8) * ALD + k + 4]);
                al[0] = __float_as_uint(Al[r0 * ALD + k]);
                al[1] = __float_as_uint(Al[(r0 + 8) * ALD + k]);
                al[2] = __float_as_uint(Al[r0 * ALD + k + 4]);
                al[3] = __float_as_uint(Al[(r0 + 8) * ALD + k + 4]);
#pragma unroll
                for (int nt = 0; nt < 4; nt++) {
                    mma_tf32(c[mt][nt], ah, bh[nt]);
                    mma_tf32(c[mt][nt], ah, bl[nt]);
                    mma_tf32(c[mt][nt], al, bh[nt]);
                }
            }
        }
        if (it + 1 < NK) {
            sts_stage(buf ^ 1);
            __syncthreads();
        }
    }

    // Epilogue: direct float2 stores from C fragments
#pragma unroll
    for (int mt = 0; mt < 4; mt++) {
#pragma unroll
        for (int nt = 0; nt < 4; nt++) {
            int col = bx * 128 + wn * 32 + nt * 8 + 2 * tig;
            float bv0 = bias[col], bv1 = bias[col + 1];
#pragma unroll
            for (int half = 0; half < 2; half++) {
                int m = by * 128 + wm * 64 + mt * 16 + gid + half * 8;
                float v0 = c[mt][nt][half * 2 + 0] + bv0;
                float v1 = c[mt][nt][half * 2 + 1] + bv1;
                if (EPI == 0) {
                    int part = col >> 10;
                    int hh = (col >> 6) & 15;
                    int d = col & 63;
                    int b = m >> 11, t = m & (T_ - 1);
                    float* dst = (part == 0) ? g_q : (part == 1) ? g_k : g_v;
                    if (part == 0) { v0 *= 0.125f; v1 *= 0.125f; }
                    *(float2*)&dst[(((size_t)(b * H_ + hh)) * T_ + t) * DK_ + d] =
                        make_float2(v0, v1);
                } else {
                    *(float2*)&C[(size_t)m * N + col] = make_float2(v0, v1);
                }
            }
        }
    }
}

// ===========================================================================
// Flash attention, mixed-precision tf32 mma.sync:
//   S = Q K^T : single-pass, Q/K pre-rounded RNA->tf32 (score err ~7e-5 abs)
//   O = P V   : 2-pass, V split hi/lo at staging, P RNA-rounded single
// CTA: 128 q rows of one (b,h); 8 warps, warp = 16 rows x full 64-col KV tile.
// 2 CTAs/SM (89KB smem, <=128 regs).
// ===========================================================================
#define QLD 68    // (gid*68+tig) % 32 distinct
#define KLDK 68
#define KLDV 72   // (tig*72+gid) % 32 distinct
#define ATT_SMEM ((128*QLD + 64*KLDK + 2*64*KLDV) * 4)   // 89088 B

__global__ __launch_bounds__(256, 2) void attn_kernel() {
    extern __shared__ float sm[];
    float* QPs = sm;                        // 128 x QLD : Q, later P (fp32)
    float* Kt  = sm + 128 * QLD;            // 64 x KLDK (tf32-rounded bits)
    float* Vh  = Kt + 64 * KLDK;            // 64 x KLDV
    float* Vl  = Vh + 64 * KLDV;

    const int tid = threadIdx.x;
    const int wid = tid >> 5, lane = tid & 31;
    const int gid = lane >> 2, tig = lane & 3;
    const int bh = blockIdx.y;
    const int t0 = blockIdx.x * 128;
    const float* qb = g_q + (size_t)bh * T_ * DK_;
    const float* kb = g_k + (size_t)bh * T_ * DK_;
    const float* vb = g_v + (size_t)bh * T_ * DK_;

    // ---- load Q tile (fp32) to smem, then prefetch+round this warp's A-frags
#pragma unroll
    for (int i = 0; i < 8; i++) {
        int idx = i * 256 + tid;
        int row = idx >> 4, dg = (idx & 15) * 4;
        *(float4*)&QPs[row * QLD + dg] =
            *(const float4*)&qb[(size_t)(t0 + row) * DK_ + dg];
    }
    __syncthreads();

    uint32_t qh[8][4];
    {
        const int r0 = wid * 16 + gid;
#pragma unroll
        for (int kk = 0; kk < 8; kk++) {
            qh[kk][0] = rna(QPs[r0 * QLD + kk * 8 + tig]);
            qh[kk][1] = rna(QPs[(r0 + 8) * QLD + kk * 8 + tig]);
            qh[kk][2] = rna(QPs[r0 * QLD + kk * 8 + tig + 4]);
            qh[kk][3] = rna(QPs[(r0 + 8) * QLD + kk * 8 + tig + 4]);
        }
    }

    float m_i[2] = {-1e30f, -1e30f};
    float l_i[2] = {0.f, 0.f};
    float oc[8][4];
#pragma unroll
    for (int j = 0; j < 8; j++)
#pragma unroll
        for (int i = 0; i < 4; i++) oc[j][i] = 0.f;

    for (int kt = 0; kt < T_ / 64; kt++) {
        __syncthreads();   // prior tile's K/V reads done by all warps
        // ---- stage K (rna-tf32) and V (hi/lo split)
#pragma unroll
        for (int i = 0; i < 4; i++) {
            int idx = i * 256 + tid;
            int row = idx >> 4, dg = (idx & 15) * 4;
            float4 kv4 = *(const float4*)&kb[(size_t)(kt * 64 + row) * DK_ + dg];
            float4 kr;
            kr.x = __uint_as_float(rna(kv4.x));
            kr.y = __uint_as_float(rna(kv4.y));
            kr.z = __uint_as_float(rna(kv4.z));
            kr.w = __uint_as_float(rna(kv4.w));
            *(float4*)&Kt[row * KLDK + dg] = kr;
            float4 vv4 = *(const float4*)&vb[(size_t)(kt * 64 + row) * DK_ + dg];
            float4 h4, l4;
            split4(vv4, h4, l4);
            *(float4*)&Vh[row * KLDV + dg] = h4;
            *(float4*)&Vl[row * KLDV + dg] = l4;
        }
        __syncthreads();

        // ---- S = Q @ K^T (single pass)
        float sc[8][4];
#pragma unroll
        for (int j = 0; j < 8; j++)
#pragma unroll
            for (int i = 0; i < 4; i++) sc[j][i] = 0.f;
#pragma unroll
        for (int kk = 0; kk < 8; kk++) {
            uint32_t bf[8][2];
#pragma unroll
            for (int j = 0; j < 8; j++) {
                int r = j * 8 + gid, k = kk * 8 + tig;
                bf[j][0] = __float_as_uint(Kt[r * KLDK + k]);
                bf[j][1] = __float_as_uint(Kt[r * KLDK + k + 4]);
            }
#pragma unroll
            for (int j = 0; j < 8; j++) mma_tf32(sc[j], qh[kk], bf[j]);
        }

        // ---- online softmax (rows gid and gid+8 of this warp's strip)
#pragma unroll
        for (int h2 = 0; h2 < 2; h2++) {
            float tmax = -1e30f;
#pragma unroll
            for (int j = 0; j < 8; j++)
                tmax = fmaxf(tmax, fmaxf(sc[j][2 * h2], sc[j][2 * h2 + 1]));
            tmax = fmaxf(tmax, __shfl_xor_sync(0xffffffffu, tmax, 1));
            tmax = fmaxf(tmax, __shfl_xor_sync(0xffffffffu, tmax, 2));
            float mn = fmaxf(m_i[h2], tmax);
            float corr = __expf(m_i[h2] - mn);
            m_i[h2] = mn;
            float ls = 0.f;
#pragma unroll
            for (int j = 0; j < 8; j++) {
                float e0 = __expf(sc[j][2 * h2] - mn);
                float e1 = __expf(sc[j][2 * h2 + 1] - mn);
                sc[j][2 * h2] = e0;
                sc[j][2 * h2 + 1] = e1;
                ls += e0 + e1;
            }
            ls += __shfl_xor_sync(0xffffffffu, ls, 1);
            ls += __shfl_xor_sync(0xffffffffu, ls, 2);
            l_i[h2] = l_i[h2] * corr + ls;
#pragma unroll
            for (int j = 0; j < 8; j++) {
                oc[j][2 * h2] *= corr;
                oc[j][2 * h2 + 1] *= corr;
            }
            int row = wid * 16 + gid + h2 * 8;
#pragma unroll
            for (int j = 0; j < 8; j++)
                *(float2*)&QPs[row * QLD + j * 8 + 2 * tig] =
                    make_float2(sc[j][2 * h2], sc[j][2 * h2 + 1]);
        }
        __syncwarp();

        // ---- O += P @ V : P rna single, V hi/lo (2 passes)
#pragma unroll
        for (int kk = 0; kk < 8; kk++) {
            uint32_t ph[4];
            const int r0 = wid * 16 + gid;
            ph[0] = rna(QPs[r0 * QLD + kk * 8 + tig]);
            ph[1] = rna(QPs[(r0 + 8) * QLD + kk * 8 + tig]);
            ph[2] = rna(QPs[r0 * QLD + kk * 8 + tig + 4]);
            ph[3] = rna(QPs[(r0 + 8) * QLD + kk * 8 + tig + 4]);
            uint32_t bhf[8][2], blf[8][2];
#pragma unroll
            for (int j = 0; j < 8; j++) {
                int k = kk * 8 + tig, n = j * 8 + gid;
                bhf[j][0] = __float_as_uint(Vh[k * KLDV + n]);
                bhf[j][1] = __float_as_uint(Vh[(k + 4) * KLDV + n]);
                blf[j][0] = __float_as_uint(Vl[k * KLDV + n]);
                blf[j][1] = __float_as_uint(Vl[(k + 4) * KLDV + n]);
            }
#pragma unroll
            for (int j = 0; j < 8; j++) {
                mma_tf32(oc[j], ph, bhf[j]);
                mma_tf32(oc[j], ph, blf[j]);
            }
        }
        __syncwarp();   // P reads done before next tile overwrites (warp-local)
    }

    // ---- finalize and write ctx (B,T,D) with head interleave
    const int b = bh >> 4, h = bh & 15;
    float inv0 = 1.0f / l_i[0], inv1 = 1.0f / l_i[1];
#pragma unroll
    for (int half = 0; half < 2; half++) {
        int t = t0 + wid * 16 + gid + half * 8;
        float inv = half ? inv1 : inv0;
        float* dst = &g_ctx[((size_t)(b * T_ + t)) * D_ + h * 64];
#pragma unroll
        for (int j = 0; j < 8; j++)
            *(float2*)&dst[j * 8 + 2 * tig] =
                make_float2(oc[j][half * 2] * inv, oc[j][half * 2 + 1] * inv);
    }
}

// ---------------------------------------------------------------------------
extern "C" void kernel_launch(void* const* d_in, const int* in_sizes, int n_in,
                              void* d_out, int out_size) {
    const float *x = nullptr, *w_qkv = nullptr, *b_qkv = nullptr,
                *w_out = nullptr, *b_out = nullptr;
    for (int i = 0; i < n_in; i++) {
        switch (in_sizes[i]) {
            case M_ * D_:   x = (const float*)d_in[i]; break;
            case D_ * N3_:  w_qkv = (const float*)d_in[i]; break;
            case N3_:       b_qkv = (const float*)d_in[i]; break;
            case D_ * D_:   w_out = (const float*)d_in[i]; break;
            case D_:        b_out = (const float*)d_in[i]; break;
        }
    }

    cudaFuncSetAttribute(gemm_tc<N3_, 0>,
                         cudaFuncAttributeMaxDynamicSharedMemorySize, GEMM_SMEM);
    cudaFuncSetAttribute(gemm_tc<D_, 1>,
                         cudaFuncAttributeMaxDynamicSharedMemorySize, GEMM_SMEM);
    cudaFuncSetAttribute(attn_kernel,
                         cudaFuncAttributeMaxDynamicSharedMemorySize, ATT_SMEM);

    gemm_tc<N3_, 0><<<dim3(N3_ / 128, M_ / 128), 256, GEMM_SMEM>>>(
        x, w_qkv, b_qkv, nullptr);
    attn_kernel<<<dim3(T_ / 128, B_ * H_), 256, ATT_SMEM>>>();
    gemm_tc<D_, 1><<<dim3(D_ / 128, M_ / 128), 256, GEMM_SMEM>>>(
        nullptr, w_out, b_out, (float*)d_out);
}

// round 6
// speedup vs baseline: 2.8984x; 1.3229x over previous
#include <cuda_runtime.h>
#include <stdint.h>

#define B_  4
#define T_  2048
#define D_  1024
#define H_  16
#define DK_ 64
#define N3_ 3072
#define M_  (B_*T_)   // 8192

// Scratch (device globals; no allocations allowed)
__device__ float g_q[B_*H_*T_*DK_];   // (b,h,t,d) pre-scaled by 1/8
__device__ float g_k[B_*H_*T_*DK_];
__device__ float g_v[B_*H_*T_*DK_];
__device__ float g_ctx[M_*D_];        // (b,t,D)

// ===========================================================================
// Helpers
// ===========================================================================
__device__ __forceinline__ void mma_tf32(float* c, const uint32_t* a,
                                         const uint32_t* b) {
    asm volatile(
        "mma.sync.aligned.m16n8k8.row.col.f32.tf32.tf32.f32 "
        "{%0,%1,%2,%3}, {%4,%5,%6,%7}, {%8,%9}, {%0,%1,%2,%3};\n"
        : "+f"(c[0]), "+f"(c[1]), "+f"(c[2]), "+f"(c[3])
        : "r"(a[0]), "r"(a[1]), "r"(a[2]), "r"(a[3]), "r"(b[0]), "r"(b[1]));
}

// m16n8k16 bf16: a = 4 regs (bf16x2 along k), b = 2 regs, c = 4 f32
__device__ __forceinline__ void mma_bf16(float* c, const uint32_t* a,
                                         const uint32_t* b) {
    asm volatile(
        "mma.sync.aligned.m16n8k16.row.col.f32.bf16.bf16.f32 "
        "{%0,%1,%2,%3}, {%4,%5,%6,%7}, {%8,%9}, {%0,%1,%2,%3};\n"
        : "+f"(c[0]), "+f"(c[1]), "+f"(c[2]), "+f"(c[3])
        : "r"(a[0]), "r"(a[1]), "r"(a[2]), "r"(a[3]), "r"(b[0]), "r"(b[1]));
}

__device__ __forceinline__ uint32_t rna(float x) {
    uint32_t r;
    asm("cvt.rna.tf32.f32 %0, %1;" : "=r"(r) : "f"(x));
    return r;
}

__device__ __forceinline__ void split_tf32(float x, uint32_t& hi, uint32_t& lo) {
    uint32_t h = rna(x);
    float r = x - __uint_as_float(h);
    hi = h; lo = rna(r);
}

__device__ __forceinline__ void split4(float4 v, float4& h4, float4& l4) {
    uint32_t h, l;
    split_tf32(v.x, h, l); h4.x = __uint_as_float(h); l4.x = __uint_as_float(l);
    split_tf32(v.y, h, l); h4.y = __uint_as_float(h); l4.y = __uint_as_float(l);
    split_tf32(v.z, h, l); h4.z = __uint_as_float(h); l4.z = __uint_as_float(l);
    split_tf32(v.w, h, l); h4.w = __uint_as_float(h); l4.w = __uint_as_float(l);
}

// pack two fp32 -> bf16x2 (even k in low half, odd k in high half)
__device__ __forceinline__ uint32_t pack_bf16(float ev, float od) {
    uint32_t r;
    asm("cvt.rn.bf16x2.f32 %0, %1, %2;" : "=r"(r) : "f"(od), "f"(ev));
    return r;
}
__device__ __forceinline__ float bf_lo(uint32_t p) { return __uint_as_float(p << 16); }
__device__ __forceinline__ float bf_hi(uint32_t p) { return __uint_as_float(p & 0xFFFF0000u); }

// hi/lo bf16x2 split of a (k_even, k_odd) fp32 pair; residuals are exact subs
__device__ __forceinline__ void split_pair(float ev, float od,
                                           uint32_t& hp, uint32_t& lp) {
    uint32_t h = pack_bf16(ev, od);
    float re = ev - bf_lo(h);
    float ro = od - bf_hi(h);
    hp = h; lp = pack_bf16(re, ro);
}

// ===========================================================================
// 3xBF16 GEMM: C[M,N] = A[M,1024] @ B[1024,N] + bias   (~fp32 accuracy)
// CTA tile 128x128, BK=16, double-buffered, 2 CTAs/SM, m16n8k16 bf16 HMMA.
// A smem: [row][pair0..7] stride 12 u32 (conflict-free frags).
// B smem: [col][slot] stride 12 u32, slot = (pair + (col>>3)) & 7
//         (conflict-free staging STS AND fragment LDS; b1 slot = b0 slot ^ 4).
// EPI 0: scatter into g_q/g_k/g_v (q scaled 1/8); EPI 1: plain store.
// ===========================================================================
#define BK   16
#define TSZ  (128 * 12)                   // u32 per tile buffer
#define GEMM_SMEM (8 * TSZ * 4)           // 49152 B (AH,AL,BH,BL x2 buffers)

template<int N, int EPI>
__global__ __launch_bounds__(256, 2) void gemm_tc(const float* __restrict__ A_in,
                                                  const float* __restrict__ Bg,
                                                  const float* __restrict__ bias,
                                                  float* __restrict__ C) {
    extern __shared__ uint32_t smu[];
    uint32_t* AH0 = smu;               // [2][TSZ]
    uint32_t* AL0 = smu + 2 * TSZ;
    uint32_t* BH0 = smu + 4 * TSZ;
    uint32_t* BL0 = smu + 6 * TSZ;

    const int tid = threadIdx.x;
    const int wid = tid >> 5, lane = tid & 31;
    const int gid = lane >> 2, tig = lane & 3;
    const int wm = wid & 1, wn = wid >> 1;      // 2 x 4 warp grid
    const int bx = blockIdx.x, by = blockIdx.y;

    const float* A = (EPI == 1) ? (const float*)g_ctx : A_in;
    const float* Abase = A + (size_t)(by * 128) * D_;
    const float* Bbase = Bg + bx * 128;

    // A staging: thread -> rows (rowA, rowA+64), k-pairs (pA, pA+1)
    const int rowA = tid >> 2, pA = (tid & 3) * 2;
    // B staging: thread -> cols (c2, c2+1), pairs (qB, qB+4)
    const int qB = tid >> 6, c2 = (tid & 63) * 2;

    float c[4][4][4];
#pragma unroll
    for (int mt = 0; mt < 4; mt++)
#pragma unroll
        for (int nt = 0; nt < 4; nt++)
#pragma unroll
            for (int i = 0; i < 4; i++) c[mt][nt][i] = 0.f;

    float4 pa0, pa1;
    float2 pb[4];     // rows 2qB, 2qB+1, 2qB+8, 2qB+9 at cols c2,c2+1
    auto ldg_stage = [&](int k0) {
        pa0 = *(const float4*)(Abase + (size_t)rowA * D_ + k0 + pA * 2);
        pa1 = *(const float4*)(Abase + (size_t)(rowA + 64) * D_ + k0 + pA * 2);
        pb[0] = *(const float2*)(Bbase + (size_t)(k0 + 2 * qB) * N + c2);
        pb[1] = *(const float2*)(Bbase + (size_t)(k0 + 2 * qB + 1) * N + c2);
        pb[2] = *(const float2*)(Bbase + (size_t)(k0 + 2 * qB + 8) * N + c2);
        pb[3] = *(const float2*)(Bbase + (size_t)(k0 + 2 * qB + 9) * N + c2);
    };
    auto sts_stage = [&](int buf) {
        uint32_t* AH = AH0 + buf * TSZ;
        uint32_t* AL = AL0 + buf * TSZ;
        uint32_t* BH = BH0 + buf * TSZ;
        uint32_t* BL = BL0 + buf * TSZ;
        uint32_t hp, lp;
        split_pair(pa0.x, pa0.y, hp, lp);
        AH[rowA * 12 + pA] = hp;      AL[rowA * 12 + pA] = lp;
        split_pair(pa0.z, pa0.w, hp, lp);
        AH[rowA * 12 + pA + 1] = hp;  AL[rowA * 12 + pA + 1] = lp;
        split_pair(pa1.x, pa1.y, hp, lp);
        AH[(rowA + 64) * 12 + pA] = hp;      AL[(rowA + 64) * 12 + pA] = lp;
        split_pair(pa1.z, pa1.w, hp, lp);
        AH[(rowA + 64) * 12 + pA + 1] = hp;  AL[(rowA + 64) * 12 + pA + 1] = lp;
        // B: (col, pair) -> slot = (pair + (col>>3)) & 7
#pragma unroll
        for (int cc = 0; cc < 2; cc++) {
            int col = c2 + cc;
            int rot = (col >> 3) & 7;
            float e0 = cc ? pb[0].y : pb[0].x;   // k = 2qB
            float o0 = cc ? pb[1].y : pb[1].x;   // k = 2qB+1
            float e1 = cc ? pb[2].y : pb[2].x;   // k = 2qB+8
            float o1 = cc ? pb[3].y : pb[3].x;   // k = 2qB+9
            split_pair(e0, o0, hp, lp);
            int s = col * 12 + ((qB + rot) & 7);
            BH[s] = hp; BL[s] = lp;
            split_pair(e1, o1, hp, lp);
            s = col * 12 + ((qB + 4 + rot) & 7);
            BH[s] = hp; BL[s] = lp;
        }
    };

    const int NK = D_ / BK;      // 64
    ldg_stage(0);
    sts_stage(0);
    __syncthreads();

    for (int it = 0; it < NK; it++) {
        const int buf = it & 1;
        if (it + 1 < NK) ldg_stage((it + 1) * BK);

        const uint32_t* AH = AH0 + buf * TSZ;
        const uint32_t* AL = AL0 + buf * TSZ;
        const uint32_t* BH = BH0 + buf * TSZ;
        const uint32_t* BL = BL0 + buf * TSZ;

        uint32_t bh[4][2], bl[4][2];
#pragma unroll
        for (int nt = 0; nt < 4; nt++) {
            const int col = wn * 32 + nt * 8 + gid;
            const int R = (wn * 4 + nt) & 7;       // (col>>3)&7, warp-const
            const int s0 = (tig + R) & 7;
            bh[nt][0] = BH[col * 12 + s0];
            bh[nt][1] = BH[col * 12 + (s0 ^ 4)];
            bl[nt][0] = BL[col * 12 + s0];
            bl[nt][1] = BL[col * 12 + (s0 ^ 4)];
        }
#pragma unroll
        for (int mt = 0; mt < 4; mt++) {
            const int r0 = wm * 64 + mt * 16 + gid;
            uint32_t ah[4], al[4];
            ah[0] = AH[r0 * 12 + tig];
            ah[1] = AH[(r0 + 8) * 12 + tig];
            ah[2] = AH[r0 * 12 + 4 + tig];
            ah[3] = AH[(r0 + 8) * 12 + 4 + tig];
            al[0] = AL[r0 * 12 + tig];
            al[1] = AL[(r0 + 8) * 12 + tig];
            al[2] = AL[r0 * 12 + 4 + tig];
            al[3] = AL[(r0 + 8) * 12 + 4 + tig];
#pragma unroll
            for (int nt = 0; nt < 4; nt++) {
                mma_bf16(c[mt][nt], ah, bh[nt]);
                mma_bf16(c[mt][nt], ah, bl[nt]);
                mma_bf16(c[mt][nt], al, bh[nt]);
            }
        }
        if (it + 1 < NK) {
            sts_stage(buf ^ 1);
            __syncthreads();
        }
    }

    // Epilogue: direct float2 stores from C fragments
#pragma unroll
    for (int mt = 0; mt < 4; mt++) {
#pragma unroll
        for (int nt = 0; nt < 4; nt++) {
            int col = bx * 128 + wn * 32 + nt * 8 + 2 * tig;
            float bv0 = bias[col], bv1 = bias[col + 1];
#pragma unroll
            for (int half = 0; half < 2; half++) {
                int m = by * 128 + wm * 64 + mt * 16 + gid + half * 8;
                float v0 = c[mt][nt][half * 2 + 0] + bv0;
                float v1 = c[mt][nt][half * 2 + 1] + bv1;
                if (EPI == 0) {
                    int part = col >> 10;
                    int hh = (col >> 6) & 15;
                    int d = col & 63;
                    int b = m >> 11, t = m & (T_ - 1);
                    float* dst = (part == 0) ? g_q : (part == 1) ? g_k : g_v;
                    if (part == 0) { v0 *= 0.125f; v1 *= 0.125f; }
                    *(float2*)&dst[(((size_t)(b * H_ + hh)) * T_ + t) * DK_ + d] =
                        make_float2(v0, v1);
                } else {
                    *(float2*)&C[(size_t)m * N + col] = make_float2(v0, v1);
                }
            }
        }
    }
}

// ===========================================================================
// Flash attention (unchanged from R5 — known-good).
//   S = Q K^T : single-pass tf32, RNA-rounded
//   O = P V   : 2-pass, V split hi/lo tf32, P RNA single
// ===========================================================================
#define QLD 68
#define KLDK 68
#define KLDV 72
#define ATT_SMEM ((128*QLD + 64*KLDK + 2*64*KLDV) * 4)   // 89088 B

__global__ __launch_bounds__(256, 2) void attn_kernel() {
    extern __shared__ float sm[];
    float* QPs = sm;
    float* Kt  = sm + 128 * QLD;
    float* Vh  = Kt + 64 * KLDK;
    float* Vl  = Vh + 64 * KLDV;

    const int tid = threadIdx.x;
    const int wid = tid >> 5, lane = tid & 31;
    const int gid = lane >> 2, tig = lane & 3;
    const int bh = blockIdx.y;
    const int t0 = blockIdx.x * 128;
    const float* qb = g_q + (size_t)bh * T_ * DK_;
    const float* kb = g_k + (size_t)bh * T_ * DK_;
    const float* vb = g_v + (size_t)bh * T_ * DK_;

#pragma unroll
    for (int i = 0; i < 8; i++) {
        int idx = i * 256 + tid;
        int row = idx >> 4, dg = (idx & 15) * 4;
        *(float4*)&QPs[row * QLD + dg] =
            *(const float4*)&qb[(size_t)(t0 + row) * DK_ + dg];
    }
    __syncthreads();

    uint32_t qh[8][4];
    {
        const int r0 = wid * 16 + gid;
#pragma unroll
        for (int kk = 0; kk < 8; kk++) {
            qh[kk][0] = rna(QPs[r0 * QLD + kk * 8 + tig]);
            qh[kk][1] = rna(QPs[(r0 + 8) * QLD + kk * 8 + tig]);
            qh[kk][2] = rna(QPs[r0 * QLD + kk * 8 + tig + 4]);
            qh[kk][3] = rna(QPs[(r0 + 8) * QLD + kk * 8 + tig + 4]);
        }
    }

    float m_i[2] = {-1e30f, -1e30f};
    float l_i[2] = {0.f, 0.f};
    float oc[8][4];
#pragma unroll
    for (int j = 0; j < 8; j++)
#pragma unroll
        for (int i = 0; i < 4; i++) oc[j][i] = 0.f;

    for (int kt = 0; kt < T_ / 64; kt++) {
        __syncthreads();
#pragma unroll
        for (int i = 0; i < 4; i++) {
            int idx = i * 256 + tid;
            int row = idx >> 4, dg = (idx & 15) * 4;
            float4 kv4 = *(const float4*)&kb[(size_t)(kt * 64 + row) * DK_ + dg];
            float4 kr;
            kr.x = __uint_as_float(rna(kv4.x));
            kr.y = __uint_as_float(rna(kv4.y));
            kr.z = __uint_as_float(rna(kv4.z));
            kr.w = __uint_as_float(rna(kv4.w));
            *(float4*)&Kt[row * KLDK + dg] = kr;
            float4 vv4 = *(const float4*)&vb[(size_t)(kt * 64 + row) * DK_ + dg];
            float4 h4, l4;
            split4(vv4, h4, l4);
            *(float4*)&Vh[row * KLDV + dg] = h4;
            *(float4*)&Vl[row * KLDV + dg] = l4;
        }
        __syncthreads();

        float sc[8][4];
#pragma unroll
        for (int j = 0; j < 8; j++)
#pragma unroll
            for (int i = 0; i < 4; i++) sc[j][i] = 0.f;
#pragma unroll
        for (int kk = 0; kk < 8; kk++) {
            uint32_t bf[8][2];
#pragma unroll
            for (int j = 0; j < 8; j++) {
                int r = j * 8 + gid, k = kk * 8 + tig;
                bf[j][0] = __float_as_uint(Kt[r * KLDK + k]);
                bf[j][1] = __float_as_uint(Kt[r * KLDK + k + 4]);
            }
#pragma unroll
            for (int j = 0; j < 8; j++) mma_tf32(sc[j], qh[kk], bf[j]);
        }

#pragma unroll
        for (int h2 = 0; h2 < 2; h2++) {
            float tmax = -1e30f;
#pragma unroll
            for (int j = 0; j < 8; j++)
                tmax = fmaxf(tmax, fmaxf(sc[j][2 * h2], sc[j][2 * h2 + 1]));
            tmax = fmaxf(tmax, __shfl_xor_sync(0xffffffffu, tmax, 1));
            tmax = fmaxf(tmax, __shfl_xor_sync(0xffffffffu, tmax, 2));
            float mn = fmaxf(m_i[h2], tmax);
            float corr = __expf(m_i[h2] - mn);
            m_i[h2] = mn;
            float ls = 0.f;
#pragma unroll
            for (int j = 0; j < 8; j++) {
                float e0 = __expf(sc[j][2 * h2] - mn);
                float e1 = __expf(sc[j][2 * h2 + 1] - mn);
                sc[j][2 * h2] = e0;
                sc[j][2 * h2 + 1] = e1;
                ls += e0 + e1;
            }
            ls += __shfl_xor_sync(0xffffffffu, ls, 1);
            ls += __shfl_xor_sync(0xffffffffu, ls, 2);
            l_i[h2] = l_i[h2] * corr + ls;
#pragma unroll
            for (int j = 0; j < 8; j++) {
                oc[j][2 * h2] *= corr;
                oc[j][2 * h2 + 1] *= corr;
            }
            int row = wid * 16 + gid + h2 * 8;
#pragma unroll
            for (int j = 0; j < 8; j++)
                *(float2*)&QPs[row * QLD + j * 8 + 2 * tig] =
                    make_float2(sc[j][2 * h2], sc[j][2 * h2 + 1]);
        }
        __syncwarp();

#pragma unroll
        for (int kk = 0; kk < 8; kk++) {
            uint32_t ph[4];
            const int r0 = wid * 16 + gid;
            ph[0] = rna(QPs[r0 * QLD + kk * 8 + tig]);
            ph[1] = rna(QPs[(r0 + 8) * QLD + kk * 8 + tig]);
            ph[2] = rna(QPs[r0 * QLD + kk * 8 + tig + 4]);
            ph[3] = rna(QPs[(r0 + 8) * QLD + kk * 8 + tig + 4]);
            uint32_t bhf[8][2], blf[8][2];
#pragma unroll
            for (int j = 0; j < 8; j++) {
                int k = kk * 8 + tig, n = j * 8 + gid;
                bhf[j][0] = __float_as_uint(Vh[k * KLDV + n]);
                bhf[j][1] = __float_as_uint(Vh[(k + 4) * KLDV + n]);
                blf[j][0] = __float_as_uint(Vl[k * KLDV + n]);
                blf[j][1] = __float_as_uint(Vl[(k + 4) * KLDV + n]);
            }
#pragma unroll
            for (int j = 0; j < 8; j++) {
                mma_tf32(oc[j], ph, bhf[j]);
                mma_tf32(oc[j], ph, blf[j]);
            }
        }
        __syncwarp();
    }

    const int b = bh >> 4, h = bh & 15;
    float inv0 = 1.0f / l_i[0], inv1 = 1.0f / l_i[1];
#pragma unroll
    for (int half = 0; half < 2; half++) {
        int t = t0 + wid * 16 + gid + half * 8;
        float inv = half ? inv1 : inv0;
        float* dst = &g_ctx[((size_t)(b * T_ + t)) * D_ + h * 64];
#pragma unroll
        for (int j = 0; j < 8; j++)
            *(float2*)&dst[j * 8 + 2 * tig] =
                make_float2(oc[j][half * 2] * inv, oc[j][half * 2 + 1] * inv);
    }
}

// ---------------------------------------------------------------------------
extern "C" void kernel_launch(void* const* d_in, const int* in_sizes, int n_in,
                              void* d_out, int out_size) {
    const float *x = nullptr, *w_qkv = nullptr, *b_qkv = nullptr,
                *w_out = nullptr, *b_out = nullptr;
    for (int i = 0; i < n_in; i++) {
        switch (in_sizes[i]) {
            case M_ * D_:   x = (const float*)d_in[i]; break;
            case D_ * N3_:  w_qkv = (const float*)d_in[i]; break;
            case N3_:       b_qkv = (const float*)d_in[i]; break;
            case D_ * D_:   w_out = (const float*)d_in[i]; break;
            case D_:        b_out = (const float*)d_in[i]; break;
        }
    }

    cudaFuncSetAttribute(gemm_tc<N3_, 0>,
                         cudaFuncAttributeMaxDynamicSharedMemorySize, GEMM_SMEM);
    cudaFuncSetAttribute(gemm_tc<D_, 1>,
                         cudaFuncAttributeMaxDynamicSharedMemorySize, GEMM_SMEM);
    cudaFuncSetAttribute(attn_kernel,
                         cudaFuncAttributeMaxDynamicSharedMemorySize, ATT_SMEM);

    gemm_tc<N3_, 0><<<dim3(N3_ / 128, M_ / 128), 256, GEMM_SMEM>>>(
        x, w_qkv, b_qkv, nullptr);
    attn_kernel<<<dim3(T_ / 128, B_ * H_), 256, ATT_SMEM>>>();
    gemm_tc<D_, 1><<<dim3(D_ / 128, M_ / 128), 256, GEMM_SMEM>>>(
        nullptr, w_out, b_out, (float*)d_out);
}

// round 8
// speedup vs baseline: 3.2988x; 1.1381x over previous
#include <cuda_runtime.h>
#include <stdint.h>

#define B_  4
#define T_  2048
#define D_  1024
#define H_  16
#define DK_ 64
#define N3_ 3072
#define M_  (B_*T_)   // 8192

// Scratch (device globals; no allocations allowed)
__device__ float g_q[B_*H_*T_*DK_];   // (b,h,t,d) pre-scaled by 1/8
__device__ float g_k[B_*H_*T_*DK_];
__device__ float g_v[B_*H_*T_*DK_];
__device__ float g_ctx[M_*D_];        // (b,t,D)

// ===========================================================================
// Helpers
// ===========================================================================
__device__ __forceinline__ void mma_tf32(float* c, const uint32_t* a,
                                         const uint32_t* b) {
    asm volatile(
        "mma.sync.aligned.m16n8k8.row.col.f32.tf32.tf32.f32 "
        "{%0,%1,%2,%3}, {%4,%5,%6,%7}, {%8,%9}, {%0,%1,%2,%3};\n"
        : "+f"(c[0]), "+f"(c[1]), "+f"(c[2]), "+f"(c[3])
        : "r"(a[0]), "r"(a[1]), "r"(a[2]), "r"(a[3]), "r"(b[0]), "r"(b[1]));
}

// m16n8k16 bf16: a = 4 regs (bf16x2 along k), b = 2 regs, c = 4 f32
__device__ __forceinline__ void mma_bf16(float* c, const uint32_t* a,
                                         const uint32_t* b) {
    asm volatile(
        "mma.sync.aligned.m16n8k16.row.col.f32.bf16.bf16.f32 "
        "{%0,%1,%2,%3}, {%4,%5,%6,%7}, {%8,%9}, {%0,%1,%2,%3};\n"
        : "+f"(c[0]), "+f"(c[1]), "+f"(c[2]), "+f"(c[3])
        : "r"(a[0]), "r"(a[1]), "r"(a[2]), "r"(a[3]), "r"(b[0]), "r"(b[1]));
}

__device__ __forceinline__ uint32_t rna(float x) {
    uint32_t r;
    asm("cvt.rna.tf32.f32 %0, %1;" : "=r"(r) : "f"(x));
    return r;
}

// pack two fp32 -> bf16x2 (even k in low half, odd k in high half)
__device__ __forceinline__ uint32_t pack_bf16(float ev, float od) {
    uint32_t r;
    asm("cvt.rn.bf16x2.f32 %0, %1, %2;" : "=r"(r) : "f"(od), "f"(ev));
    return r;
}
__device__ __forceinline__ float bf_lo(uint32_t p) { return __uint_as_float(p << 16); }
__device__ __forceinline__ float bf_hi(uint32_t p) { return __uint_as_float(p & 0xFFFF0000u); }

// hi/lo bf16x2 split of a (k_even, k_odd) fp32 pair; residuals are exact subs
__device__ __forceinline__ void split_pair(float ev, float od,
                                           uint32_t& hp, uint32_t& lp) {
    uint32_t h = pack_bf16(ev, od);
    float re = ev - bf_lo(h);
    float ro = od - bf_hi(h);
    hp = h; lp = pack_bf16(re, ro);
}

// ===========================================================================
// 3xBF16 GEMM (unchanged from R6): C[M,N] = A[M,1024] @ B[1024,N] + bias
// ===========================================================================
#define BK   16
#define TSZ  (128 * 12)                   // u32 per tile buffer
#define GEMM_SMEM (8 * TSZ * 4)           // 49152 B

template<int N, int EPI>
__global__ __launch_bounds__(256, 2) void gemm_tc(const float* __restrict__ A_in,
                                                  const float* __restrict__ Bg,
                                                  const float* __restrict__ bias,
                                                  float* __restrict__ C) {
    extern __shared__ uint32_t smu[];
    uint32_t* AH0 = smu;               // [2][TSZ]
    uint32_t* AL0 = smu + 2 * TSZ;
    uint32_t* BH0 = smu + 4 * TSZ;
    uint32_t* BL0 = smu + 6 * TSZ;

    const int tid = threadIdx.x;
    const int wid = tid >> 5, lane = tid & 31;
    const int gid = lane >> 2, tig = lane & 3;
    const int wm = wid & 1, wn = wid >> 1;
    const int bx = blockIdx.x, by = blockIdx.y;

    const float* A = (EPI == 1) ? (const float*)g_ctx : A_in;
    const float* Abase = A + (size_t)(by * 128) * D_;
    const float* Bbase = Bg + bx * 128;

    const int rowA = tid >> 2, pA = (tid & 3) * 2;
    const int qB = tid >> 6, c2 = (tid & 63) * 2;

    float c[4][4][4];
#pragma unroll
    for (int mt = 0; mt < 4; mt++)
#pragma unroll
        for (int nt = 0; nt < 4; nt++)
#pragma unroll
            for (int i = 0; i < 4; i++) c[mt][nt][i] = 0.f;

    float4 pa0, pa1;
    float2 pb[4];
    auto ldg_stage = [&](int k0) {
        pa0 = *(const float4*)(Abase + (size_t)rowA * D_ + k0 + pA * 2);
        pa1 = *(const float4*)(Abase + (size_t)(rowA + 64) * D_ + k0 + pA * 2);
        pb[0] = *(const float2*)(Bbase + (size_t)(k0 + 2 * qB) * N + c2);
        pb[1] = *(const float2*)(Bbase + (size_t)(k0 + 2 * qB + 1) * N + c2);
        pb[2] = *(const float2*)(Bbase + (size_t)(k0 + 2 * qB + 8) * N + c2);
        pb[3] = *(const float2*)(Bbase + (size_t)(k0 + 2 * qB + 9) * N + c2);
    };
    auto sts_stage = [&](int buf) {
        uint32_t* AH = AH0 + buf * TSZ;
        uint32_t* AL = AL0 + buf * TSZ;
        uint32_t* BH = BH0 + buf * TSZ;
        uint32_t* BL = BL0 + buf * TSZ;
        uint32_t hp, lp;
        split_pair(pa0.x, pa0.y, hp, lp);
        AH[rowA * 12 + pA] = hp;      AL[rowA * 12 + pA] = lp;
        split_pair(pa0.z, pa0.w, hp, lp);
        AH[rowA * 12 + pA + 1] = hp;  AL[rowA * 12 + pA + 1] = lp;
        split_pair(pa1.x, pa1.y, hp, lp);
        AH[(rowA + 64) * 12 + pA] = hp;      AL[(rowA + 64) * 12 + pA] = lp;
        split_pair(pa1.z, pa1.w, hp, lp);
        AH[(rowA + 64) * 12 + pA + 1] = hp;  AL[(rowA + 64) * 12 + pA + 1] = lp;
#pragma unroll
        for (int cc = 0; cc < 2; cc++) {
            int col = c2 + cc;
            int rot = (col >> 3) & 7;
            float e0 = cc ? pb[0].y : pb[0].x;
            float o0 = cc ? pb[1].y : pb[1].x;
            float e1 = cc ? pb[2].y : pb[2].x;
            float o1 = cc ? pb[3].y : pb[3].x;
            split_pair(e0, o0, hp, lp);
            int s = col * 12 + ((qB + rot) & 7);
            BH[s] = hp; BL[s] = lp;
            split_pair(e1, o1, hp, lp);
            s = col * 12 + ((qB + 4 + rot) & 7);
            BH[s] = hp; BL[s] = lp;
        }
    };

    const int NK = D_ / BK;      // 64
    ldg_stage(0);
    sts_stage(0);
    __syncthreads();

    for (int it = 0; it < NK; it++) {
        const int buf = it & 1;
        if (it + 1 < NK) ldg_stage((it + 1) * BK);

        const uint32_t* AH = AH0 + buf * TSZ;
        const uint32_t* AL = AL0 + buf * TSZ;
        const uint32_t* BH = BH0 + buf * TSZ;
        const uint32_t* BL = BL0 + buf * TSZ;

        uint32_t bh[4][2], bl[4][2];
#pragma unroll
        for (int nt = 0; nt < 4; nt++) {
            const int col = wn * 32 + nt * 8 + gid;
            const int R = (wn * 4 + nt) & 7;
            const int s0 = (tig + R) & 7;
            bh[nt][0] = BH[col * 12 + s0];
            bh[nt][1] = BH[col * 12 + (s0 ^ 4)];
            bl[nt][0] = BL[col * 12 + s0];
            bl[nt][1] = BL[col * 12 + (s0 ^ 4)];
        }
#pragma unroll
        for (int mt = 0; mt < 4; mt++) {
            const int r0 = wm * 64 + mt * 16 + gid;
            uint32_t ah[4], al[4];
            ah[0] = AH[r0 * 12 + tig];
            ah[1] = AH[(r0 + 8) * 12 + tig];
            ah[2] = AH[r0 * 12 + 4 + tig];
            ah[3] = AH[(r0 + 8) * 12 + 4 + tig];
            al[0] = AL[r0 * 12 + tig];
            al[1] = AL[(r0 + 8) * 12 + tig];
            al[2] = AL[r0 * 12 + 4 + tig];
            al[3] = AL[(r0 + 8) * 12 + 4 + tig];
#pragma unroll
            for (int nt = 0; nt < 4; nt++) {
                mma_bf16(c[mt][nt], ah, bh[nt]);
                mma_bf16(c[mt][nt], ah, bl[nt]);
                mma_bf16(c[mt][nt], al, bh[nt]);
            }
        }
        if (it + 1 < NK) {
            sts_stage(buf ^ 1);
            __syncthreads();
        }
    }

#pragma unroll
    for (int mt = 0; mt < 4; mt++) {
#pragma unroll
        for (int nt = 0; nt < 4; nt++) {
            int col = bx * 128 + wn * 32 + nt * 8 + 2 * tig;
            float bv0 = bias[col], bv1 = bias[col + 1];
#pragma unroll
            for (int half = 0; half < 2; half++) {
                int m = by * 128 + wm * 64 + mt * 16 + gid + half * 8;
                float v0 = c[mt][nt][half * 2 + 0] + bv0;
                float v1 = c[mt][nt][half * 2 + 1] + bv1;
                if (EPI == 0) {
                    int part = col >> 10;
                    int hh = (col >> 6) & 15;
                    int d = col & 63;
                    int b = m >> 11, t = m & (T_ - 1);
                    float* dst = (part == 0) ? g_q : (part == 1) ? g_k : g_v;
                    if (part == 0) { v0 *= 0.125f; v1 *= 0.125f; }
                    *(float2*)&dst[(((size_t)(b * H_ + hh)) * T_ + t) * DK_ + d] =
                        make_float2(v0, v1);
                } else {
                    *(float2*)&C[(size_t)m * N + col] = make_float2(v0, v1);
                }
            }
        }
    }
}

// ===========================================================================
// Flash attention:
//   S = Q K^T : single-pass tf32 (RNA) — score err ~7e-5 abs
//   O = P V   : 3xBF16 m16n8k16; P packed DIRECTLY from S registers (no smem);
//               V staged once per tile as packed bf16x2 pairs VP[pair][n].
// VPLD = 72 u32: row holds n=0..63 (64 u32) + pad; 72 mod 32 = 8 so the frag
// LDS bank is 8*tig+gid (all 32 lanes distinct); STS.128 phases consecutive.
// K-tile register prefetch hides global latency behind compute.
// CTA: 128 q rows of one (b,h); 8 warps; 2 CTAs/SM.
// ===========================================================================
#define QLD 68
#define KLDK 68
#define VPLD 72
#define ATT_SMEM ((128*QLD + 64*KLDK) * 4 + 2 * 32 * VPLD * 4)  // 70656 B

__global__ __launch_bounds__(256, 2) void attn_kernel() {
    extern __shared__ float sm[];
    float* Qs = sm;                               // 128 x QLD
    float* Kt = sm + 128 * QLD;                   // 64 x KLDK (tf32 bits)
    uint32_t* VPh = (uint32_t*)(Kt + 64 * KLDK);  // 32 pairs x VPLD
    uint32_t* VPl = VPh + 32 * VPLD;

    const int tid = threadIdx.x;
    const int wid = tid >> 5, lane = tid & 31;
    const int gid = lane >> 2, tig = lane & 3;
    const int bh = blockIdx.y;
    const int t0 = blockIdx.x * 128;
    const float* qb = g_q + (size_t)bh * T_ * DK_;
    const float* kb = g_k + (size_t)bh * T_ * DK_;
    const float* vb = g_v + (size_t)bh * T_ * DK_;

    // V staging coords: pair vp (= 2 source rows), float4 slots vf and vf+8
    const int vp = tid >> 3, vf = tid & 7;

    // ---- load Q tile to smem, prefetch+round this warp's A-frags
#pragma unroll
    for (int i = 0; i < 8; i++) {
        int idx = i * 256 + tid;
        int row = idx >> 4, dg = (idx & 15) * 4;
        *(float4*)&Qs[row * QLD + dg] =
            *(const float4*)&qb[(size_t)(t0 + row) * DK_ + dg];
    }
    __syncthreads();

    uint32_t qh[8][4];
    {
        const int r0 = wid * 16 + gid;
#pragma unroll
        for (int kk = 0; kk < 8; kk++) {
            qh[kk][0] = rna(Qs[r0 * QLD + kk * 8 + tig]);
            qh[kk][1] = rna(Qs[(r0 + 8) * QLD + kk * 8 + tig]);
            qh[kk][2] = rna(Qs[r0 * QLD + kk * 8 + tig + 4]);
            qh[kk][3] = rna(Qs[(r0 + 8) * QLD + kk * 8 + tig + 4]);
        }
    }

    float m_i[2] = {-1e30f, -1e30f};
    float l_i[2] = {0.f, 0.f};
    float oc[8][4];
#pragma unroll
    for (int j = 0; j < 8; j++)
#pragma unroll
        for (int i = 0; i < 4; i++) oc[j][i] = 0.f;

    // K prefetch registers (4 float4 / thread; rows idx>>4, dg (idx&15)*4)
    float4 kreg[4];
    auto ldgK = [&](int kt) {
#pragma unroll
        for (int i = 0; i < 4; i++) {
            int idx = i * 256 + tid;
            int row = idx >> 4, dg = (idx & 15) * 4;
            kreg[i] = *(const float4*)&kb[(size_t)(kt * 64 + row) * DK_ + dg];
        }
    };

    ldgK(0);

    for (int kt = 0; kt < T_ / 64; kt++) {
        __syncthreads();   // prior tile's K/VP reads complete
        // ---- stage K (rna-tf32) from prefetch regs
#pragma unroll
        for (int i = 0; i < 4; i++) {
            int idx = i * 256 + tid;
            int row = idx >> 4, dg = (idx & 15) * 4;
            float4 kr;
            kr.x = __uint_as_float(rna(kreg[i].x));
            kr.y = __uint_as_float(rna(kreg[i].y));
            kr.z = __uint_as_float(rna(kreg[i].z));
            kr.w = __uint_as_float(rna(kreg[i].w));
            *(float4*)&Kt[row * KLDK + dg] = kr;
        }
        // ---- stage V as packed bf16x2 pairs: VP[pair][n], n = 0..63
        {
            const float* v0 = &vb[(size_t)(kt * 64 + 2 * vp) * DK_];
            const float* v1 = v0 + DK_;
#pragma unroll
            for (int half = 0; half < 2; half++) {
                int f = vf + half * 8;
                float4 a = *(const float4*)&v0[f * 4];
                float4 b = *(const float4*)&v1[f * 4];
                uint32_t h0, l0, h1, l1, h2, l2, h3, l3;
                split_pair(a.x, b.x, h0, l0);
                split_pair(a.y, b.y, h1, l1);
                split_pair(a.z, b.z, h2, l2);
                split_pair(a.w, b.w, h3, l3);
                *(uint4*)&VPh[vp * VPLD + f * 4] = make_uint4(h0, h1, h2, h3);
                *(uint4*)&VPl[vp * VPLD + f * 4] = make_uint4(l0, l1, l2, l3);
            }
        }
        __syncthreads();
        if (kt + 1 < T_ / 64) ldgK(kt + 1);   // overlap next K load with compute

        // ---- S = Q @ K^T (single-pass tf32)
        float sc[8][4];
#pragma unroll
        for (int j = 0; j < 8; j++)
#pragma unroll
            for (int i = 0; i < 4; i++) sc[j][i] = 0.f;
#pragma unroll
        for (int kk = 0; kk < 8; kk++) {
            uint32_t bf[8][2];
#pragma unroll
            for (int j = 0; j < 8; j++) {
                int r = j * 8 + gid, k = kk * 8 + tig;
                bf[j][0] = __float_as_uint(Kt[r * KLDK + k]);
                bf[j][1] = __float_as_uint(Kt[r * KLDK + k + 4]);
            }
#pragma unroll
            for (int j = 0; j < 8; j++) mma_tf32(sc[j], qh[kk], bf[j]);
        }

        // ---- online softmax (rows gid and gid+8 of this warp's strip)
#pragma unroll
        for (int h2 = 0; h2 < 2; h2++) {
            float tmax = -1e30f;
#pragma unroll
            for (int j = 0; j < 8; j++)
                tmax = fmaxf(tmax, fmaxf(sc[j][2 * h2], sc[j][2 * h2 + 1]));
            tmax = fmaxf(tmax, __shfl_xor_sync(0xffffffffu, tmax, 1));
            tmax = fmaxf(tmax, __shfl_xor_sync(0xffffffffu, tmax, 2));
            float mn = fmaxf(m_i[h2], tmax);
            float corr = __expf(m_i[h2] - mn);
            m_i[h2] = mn;
            float ls = 0.f;
#pragma unroll
            for (int j = 0; j < 8; j++) {
                float e0 = __expf(sc[j][2 * h2] - mn);
                float e1 = __expf(sc[j][2 * h2 + 1] - mn);
                sc[j][2 * h2] = e0;
                sc[j][2 * h2 + 1] = e1;
                ls += e0 + e1;
            }
            ls += __shfl_xor_sync(0xffffffffu, ls, 1);
            ls += __shfl_xor_sync(0xffffffffu, ls, 2);
            l_i[h2] = l_i[h2] * corr + ls;
#pragma unroll
            for (int j = 0; j < 8; j++) {
                oc[j][2 * h2] *= corr;
                oc[j][2 * h2 + 1] *= corr;
            }
        }

        // ---- O += P @ V : 3xBF16, P packed straight from sc registers
#pragma unroll
        for (int kk = 0; kk < 4; kk++) {
            uint32_t ph[4], pl[4];
            split_pair(sc[2 * kk][0],     sc[2 * kk][1],     ph[0], pl[0]);
            split_pair(sc[2 * kk][2],     sc[2 * kk][3],     ph[1], pl[1]);
            split_pair(sc[2 * kk + 1][0], sc[2 * kk + 1][1], ph[2], pl[2]);
            split_pair(sc[2 * kk + 1][2], sc[2 * kk + 1][3], ph[3], pl[3]);
            uint32_t vh[8][2], vl[8][2];
#pragma unroll
            for (int j = 0; j < 8; j++) {
                int n = j * 8 + gid;
                int p0 = 8 * kk + tig, p1 = p0 + 4;
                vh[j][0] = VPh[p0 * VPLD + n];
                vh[j][1] = VPh[p1 * VPLD + n];
                vl[j][0] = VPl[p0 * VPLD + n];
                vl[j][1] = VPl[p1 * VPLD + n];
            }
#pragma unroll
            for (int j = 0; j < 8; j++) {
                mma_bf16(oc[j], ph, vh[j]);
                mma_bf16(oc[j], ph, vl[j]);
                mma_bf16(oc[j], pl, vh[j]);
            }
        }
    }

    // ---- finalize and write ctx (B,T,D) with head interleave
    const int b = bh >> 4, h = bh & 15;
    float inv0 = 1.0f / l_i[0], inv1 = 1.0f / l_i[1];
#pragma unroll
    for (int half = 0; half < 2; half++) {
        int t = t0 + wid * 16 + gid + half * 8;
        float inv = half ? inv1 : inv0;
        float* dst = &g_ctx[((size_t)(b * T_ + t)) * D_ + h * 64];
#pragma unroll
        for (int j = 0; j < 8; j++)
            *(float2*)&dst[j * 8 + 2 * tig] =
                make_float2(oc[j][half * 2] * inv, oc[j][half * 2 + 1] * inv);
    }
}

// ---------------------------------------------------------------------------
extern "C" void kernel_launch(void* const* d_in, const int* in_sizes, int n_in,
                              void* d_out, int out_size) {
    const float *x = nullptr, *w_qkv = nullptr, *b_qkv = nullptr,
                *w_out = nullptr, *b_out = nullptr;
    for (int i = 0; i < n_in; i++) {
        switch (in_sizes[i]) {
            case M_ * D_:   x = (const float*)d_in[i]; break;
            case D_ * N3_:  w_qkv = (const float*)d_in[i]; break;
            case N3_:       b_qkv = (const float*)d_in[i]; break;
            case D_ * D_:   w_out = (const float*)d_in[i]; break;
            case D_:        b_out = (const float*)d_in[i]; break;
        }
    }

    cudaFuncSetAttribute(gemm_tc<N3_, 0>,
                         cudaFuncAttributeMaxDynamicSharedMemorySize, GEMM_SMEM);
    cudaFuncSetAttribute(gemm_tc<D_, 1>,
                         cudaFuncAttributeMaxDynamicSharedMemorySize, GEMM_SMEM);
    cudaFuncSetAttribute(attn_kernel,
                         cudaFuncAttributeMaxDynamicSharedMemorySize, ATT_SMEM);

    gemm_tc<N3_, 0><<<dim3(N3_ / 128, M_ / 128), 256, GEMM_SMEM>>>(
        x, w_qkv, b_qkv, nullptr);
    attn_kernel<<<dim3(T_ / 128, B_ * H_), 256, ATT_SMEM>>>();
    gemm_tc<D_, 1><<<dim3(D_ / 128, M_ / 128), 256, GEMM_SMEM>>>(
        nullptr, w_out, b_out, (float*)d_out);
}